// round 1
// baseline (speedup 1.0000x reference)
#include <cuda_runtime.h>
#include <math.h>

#define UU 100000
#define II 50000
#define DD 64
#define EE 2000000
#define NN 150000   // UU + II

// ---- device scratch (static; no allocation anywhere) ----
__device__ float g_x  [NN * DD];
__device__ float g_xn [NN * DD];
__device__ float g_acc[NN * DD];
__device__ int2  g_edge[2 * EE];     // {src, float_as_int(coef)} dest-sorted CSR payload
__device__ float g_deg [NN];
__device__ float g_dinv[NN];
__device__ int   g_cnt [NN];
__device__ int   g_off [NN + 1];
__device__ int   g_pos [NN];

// ---------------------------------------------------------------------------
__global__ void k_init()
{
    int i = blockIdx.x * blockDim.x + threadIdx.x;
    if (i < NN) { g_deg[i] = 1.0f; g_cnt[i] = 0; }   // 1.0 = self loop weight
}

// degree + per-node incoming-edge count (both directions of each undirected edge)
__global__ void k_edge_stats(const float* __restrict__ ew,
                             const int* __restrict__ ui,
                             const int* __restrict__ ii)
{
    int e = blockIdx.x * blockDim.x + threadIdx.x;
    if (e >= EE) return;
    float w = fmaxf(ew[e], 1e-6f);
    int u = ui[e];
    int v = ii[e] + UU;
    atomicAdd(&g_deg[u], w);
    atomicAdd(&g_deg[v], w);
    atomicAdd(&g_cnt[u], 1);
    atomicAdd(&g_cnt[v], 1);
}

__global__ void k_dinv()
{
    int i = blockIdx.x * blockDim.x + threadIdx.x;
    if (i < NN) g_dinv[i] = rsqrtf(g_deg[i]);        // deg >= 1 always
}

// single-block chunked exclusive scan of g_cnt -> g_off, init g_pos
__global__ void k_scan()
{
    __shared__ int s[1024];
    const int T = 1024;
    int t = threadIdx.x;
    int chunk = (NN + T - 1) / T;
    int beg = t * chunk;
    int end = min(beg + chunk, NN);
    int sum = 0;
    for (int i = beg; i < end; i++) sum += g_cnt[i];
    s[t] = sum;
    __syncthreads();
    // Hillis-Steele inclusive scan
    for (int d = 1; d < T; d <<= 1) {
        int v = (t >= d) ? s[t - d] : 0;
        __syncthreads();
        s[t] += v;
        __syncthreads();
    }
    int base = (t == 0) ? 0 : s[t - 1];
    for (int i = beg; i < end; i++) {
        g_off[i] = base;
        g_pos[i] = base;
        base += g_cnt[i];
    }
    if (t == T - 1) g_off[NN] = base;                // == 2*EE
}

// fill CSR: each undirected edge contributes both directions with coef c
__global__ void k_fill(const float* __restrict__ ew,
                       const int* __restrict__ ui,
                       const int* __restrict__ ii)
{
    int e = blockIdx.x * blockDim.x + threadIdx.x;
    if (e >= EE) return;
    float w = fmaxf(ew[e], 1e-6f);
    int u = ui[e];
    int v = ii[e] + UU;
    float c = g_dinv[u] * w * g_dinv[v];
    int cb = __float_as_int(c);
    int p0 = atomicAdd(&g_pos[v], 1);
    g_edge[p0] = make_int2(u, cb);
    int p1 = atomicAdd(&g_pos[u], 1);
    g_edge[p1] = make_int2(v, cb);
}

// ---------------------------------------------------------------------------
// user L0 embedding: l2norm(user_w) -> x[0:U], acc[0:U].  One warp per user.
__global__ void k_user(const float* __restrict__ uw)
{
    int warp = (blockIdx.x * blockDim.x + threadIdx.x) >> 5;
    int lane = threadIdx.x & 31;
    if (warp >= UU) return;
    float2 v = ((const float2*)(uw + (size_t)warp * DD))[lane];
    float ss = v.x * v.x + v.y * v.y;
    #pragma unroll
    for (int o = 16; o; o >>= 1) ss += __shfl_xor_sync(0xffffffffu, ss, o);
    float inv = 1.0f / fmaxf(sqrtf(ss), 1e-12f);
    float2 r = make_float2(v.x * inv, v.y * inv);
    ((float2*)(g_x   + (size_t)warp * DD))[lane] = r;
    ((float2*)(g_acc + (size_t)warp * DD))[lane] = r;
}

// item L0: l2norm( [audio | artist+album] @ W^T + b ). One warp per item,
// 8 items per 256-thread block, W^T staged k-major in shared (conflict-free).
__global__ void k_item(const float* __restrict__ audio,
                       const float* __restrict__ artw,
                       const float* __restrict__ albw,
                       const float* __restrict__ W,     // [64,128] row-major
                       const float* __restrict__ b,
                       const int* __restrict__ aid,
                       const int* __restrict__ bid)
{
    __shared__ float Wsh[128 * 64];     // Wsh[k*64+d] = W[d*128+k]
    __shared__ float fsh[8][128];
    for (int idx = threadIdx.x; idx < 128 * 64; idx += blockDim.x) {
        int d = idx & 63, k = idx >> 6;
        Wsh[idx] = W[d * 128 + k];
    }
    __syncthreads();

    int warp = threadIdx.x >> 5;
    int lane = threadIdx.x & 31;
    int item = blockIdx.x * 8 + warp;
    if (item >= II) return;

    int a = aid[item];
    int bb = bid[item];
    float2 au = ((const float2*)(audio + (size_t)item * DD))[lane];
    float2 m0 = ((const float2*)(artw  + (size_t)a    * DD))[lane];
    float2 m1 = ((const float2*)(albw  + (size_t)bb   * DD))[lane];
    ((float2*)(fsh[warp]))[lane]      = au;
    ((float2*)(fsh[warp] + 64))[lane] = make_float2(m0.x + m1.x, m0.y + m1.y);
    __syncwarp();

    float a0 = 0.f, a1 = 0.f;
    #pragma unroll
    for (int k = 0; k < 128; k++) {
        float f = fsh[warp][k];
        a0 = fmaf(f, Wsh[k * 64 + lane],      a0);
        a1 = fmaf(f, Wsh[k * 64 + lane + 32], a1);
    }
    a0 += b[lane];
    a1 += b[lane + 32];
    float ss = a0 * a0 + a1 * a1;
    #pragma unroll
    for (int o = 16; o; o >>= 1) ss += __shfl_xor_sync(0xffffffffu, ss, o);
    float inv = 1.0f / fmaxf(sqrtf(ss), 1e-12f);
    size_t row = (size_t)(UU + item) * DD;
    g_x  [row + lane]      = a0 * inv;
    g_x  [row + lane + 32] = a1 * inv;
    g_acc[row + lane]      = a0 * inv;
    g_acc[row + lane + 32] = a1 * inv;
}

// ---------------------------------------------------------------------------
// one LGConv layer: warp per dest node; pure gather + register reduce.
// parity selects ping-pong; accAdd folds the running-sum of the PREVIOUS layer.
__global__ void k_prop(int parity, int accAdd)
{
    const float* __restrict__ x  = parity ? g_xn : g_x;
    float*       __restrict__ xn = parity ? g_x  : g_xn;

    int warp = (blockIdx.x * blockDim.x + threadIdx.x) >> 5;
    int lane = threadIdx.x & 31;
    if (warp >= NN) return;
    int dest = warp;

    float2 v = ((const float2*)(x + (size_t)dest * DD))[lane];
    float di = g_dinv[dest];
    float cs = di * di;                       // self-loop coefficient
    float rx = cs * v.x, ry = cs * v.y;

    if (accAdd) {
        float2* ar = (float2*)(g_acc + (size_t)dest * DD);
        float2 a = ar[lane];
        a.x += v.x; a.y += v.y;
        ar[lane] = a;
    }

    int e   = g_off[dest];
    int end = g_off[dest + 1];
    for (; e + 4 <= end; e += 4) {
        int2 e0 = __ldg(&g_edge[e]);
        int2 e1 = __ldg(&g_edge[e + 1]);
        int2 e2 = __ldg(&g_edge[e + 2]);
        int2 e3 = __ldg(&g_edge[e + 3]);
        float2 v0 = __ldg(&((const float2*)(x + (size_t)e0.x * DD))[lane]);
        float2 v1 = __ldg(&((const float2*)(x + (size_t)e1.x * DD))[lane]);
        float2 v2 = __ldg(&((const float2*)(x + (size_t)e2.x * DD))[lane]);
        float2 v3 = __ldg(&((const float2*)(x + (size_t)e3.x * DD))[lane]);
        rx = fmaf(__int_as_float(e0.y), v0.x, rx); ry = fmaf(__int_as_float(e0.y), v0.y, ry);
        rx = fmaf(__int_as_float(e1.y), v1.x, rx); ry = fmaf(__int_as_float(e1.y), v1.y, ry);
        rx = fmaf(__int_as_float(e2.y), v2.x, rx); ry = fmaf(__int_as_float(e2.y), v2.y, ry);
        rx = fmaf(__int_as_float(e3.y), v3.x, rx); ry = fmaf(__int_as_float(e3.y), v3.y, ry);
    }
    for (; e < end; e++) {
        int2 ee = __ldg(&g_edge[e]);
        float2 vv = __ldg(&((const float2*)(x + (size_t)ee.x * DD))[lane]);
        rx = fmaf(__int_as_float(ee.y), vv.x, rx);
        ry = fmaf(__int_as_float(ee.y), vv.y, ry);
    }
    ((float2*)(xn + (size_t)dest * DD))[lane] = make_float2(rx, ry);
}

// out = l2norm( (acc + x3) / 4 ).  x3 lives in g_xn after layer 2.
__global__ void k_final(float* __restrict__ out)
{
    int warp = (blockIdx.x * blockDim.x + threadIdx.x) >> 5;
    int lane = threadIdx.x & 31;
    if (warp >= NN) return;
    float2 a  = ((const float2*)(g_acc + (size_t)warp * DD))[lane];
    float2 xl = ((const float2*)(g_xn  + (size_t)warp * DD))[lane];
    float sx = (a.x + xl.x) * 0.25f;
    float sy = (a.y + xl.y) * 0.25f;
    float ss = sx * sx + sy * sy;
    #pragma unroll
    for (int o = 16; o; o >>= 1) ss += __shfl_xor_sync(0xffffffffu, ss, o);
    float inv = 1.0f / fmaxf(sqrtf(ss), 1e-12f);
    ((float2*)(out + (size_t)warp * DD))[lane] = make_float2(sx * inv, sy * inv);
}

// ---------------------------------------------------------------------------
extern "C" void kernel_launch(void* const* d_in, const int* in_sizes, int n_in,
                              void* d_out, int out_size)
{
    const float* user_w     = (const float*)d_in[0];
    const float* item_audio = (const float*)d_in[1];
    const float* artist_w   = (const float*)d_in[2];
    const float* album_w    = (const float*)d_in[3];
    const float* proj_W     = (const float*)d_in[4];
    const float* proj_b     = (const float*)d_in[5];
    const float* edge_w     = (const float*)d_in[6];
    const int*   u_idx      = (const int*)  d_in[7];
    const int*   i_idx      = (const int*)  d_in[8];
    const int*   artist_ids = (const int*)  d_in[9];
    const int*   album_ids  = (const int*)  d_in[10];
    float* out = (float*)d_out;

    const int T = 256;
    int nBlocksN = (NN + T - 1) / T;
    int nBlocksE = (EE + T - 1) / T;
    int nWarpBlocksN = (NN * 32 + T - 1) / T;   // warp-per-node kernels
    int nWarpBlocksU = (UU * 32 + T - 1) / T;
    int nBlocksItem  = (II + 7) / 8;

    // graph build
    k_init<<<nBlocksN, T>>>();
    k_edge_stats<<<nBlocksE, T>>>(edge_w, u_idx, i_idx);
    k_dinv<<<nBlocksN, T>>>();
    k_scan<<<1, 1024>>>();
    k_fill<<<nBlocksE, T>>>(edge_w, u_idx, i_idx);

    // L0 embeddings (also initialize acc = x0)
    k_user<<<nWarpBlocksU, T>>>(user_w);
    k_item<<<nBlocksItem, T>>>(item_audio, artist_w, album_w, proj_W, proj_b,
                               artist_ids, album_ids);

    // 3 LGConv layers with fused running sum
    k_prop<<<nWarpBlocksN, T>>>(0, 0);   // x0 -> x1 (in g_xn)
    k_prop<<<nWarpBlocksN, T>>>(1, 1);   // acc += x1; x1 -> x2 (in g_x)
    k_prop<<<nWarpBlocksN, T>>>(0, 1);   // acc += x2; x2 -> x3 (in g_xn)

    // out = l2norm((acc + x3)/4)
    k_final<<<nWarpBlocksN, T>>>(out);
}

// round 2
// speedup vs baseline: 1.3420x; 1.3420x over previous
#include <cuda_runtime.h>
#include <math.h>

#define UU 100000
#define II 50000
#define DD 64
#define EE 2000000
#define NN 150000   // UU + II
#define NB 147      // ceil(NN / 1024) scan blocks

// ---- device scratch (static; no allocation anywhere) ----
__device__ float g_x  [NN * DD];
__device__ float g_xn [NN * DD];
__device__ float g_acc[NN * DD];
__device__ int2  g_edge[2 * EE];     // {src, float_as_int(coef)} dest-sorted CSR payload
__device__ float g_deg [NN];
__device__ float g_dinv[NN];
__device__ int   g_cnt [NN];
__device__ int   g_excl[NN];
__device__ int   g_bsum[256];
__device__ int   g_btop[256];
__device__ int   g_off [NN + 1];
__device__ int   g_pos [NN];

// ---------------------------------------------------------------------------
__global__ void k_init()
{
    int i = blockIdx.x * blockDim.x + threadIdx.x;
    if (i < NN) { g_deg[i] = 1.0f; g_cnt[i] = 0; }   // 1.0 = self loop weight
}

// degree + per-node incoming-edge count (both directions of each undirected edge)
__global__ void k_edge_stats(const float* __restrict__ ew,
                             const int* __restrict__ ui,
                             const int* __restrict__ ii)
{
    int e = blockIdx.x * blockDim.x + threadIdx.x;
    if (e >= EE) return;
    float w = fmaxf(ew[e], 1e-6f);
    int u = ui[e];
    int v = ii[e] + UU;
    atomicAdd(&g_deg[u], w);
    atomicAdd(&g_deg[v], w);
    atomicAdd(&g_cnt[u], 1);
    atomicAdd(&g_cnt[v], 1);
}

// ---- 3-phase multi-block exclusive scan of g_cnt -> g_off ------------------
__global__ void k_scan_block()
{
    __shared__ int s[1024];
    int t = threadIdx.x;
    int i = blockIdx.x * 1024 + t;
    int v = (i < NN) ? g_cnt[i] : 0;
    s[t] = v;
    __syncthreads();
    #pragma unroll
    for (int d = 1; d < 1024; d <<= 1) {
        int u = (t >= d) ? s[t - d] : 0;
        __syncthreads();
        s[t] += u;
        __syncthreads();
    }
    if (i < NN) g_excl[i] = s[t] - v;                // exclusive within block
    if (t == 1023) g_bsum[blockIdx.x] = s[1023];     // block total
}

__global__ void k_scan_tops()
{
    __shared__ int s[256];
    int t = threadIdx.x;
    int v = (t < NB) ? g_bsum[t] : 0;
    s[t] = v;
    __syncthreads();
    #pragma unroll
    for (int d = 1; d < 256; d <<= 1) {
        int u = (t >= d) ? s[t - d] : 0;
        __syncthreads();
        s[t] += u;
        __syncthreads();
    }
    g_btop[t] = s[t] - v;                            // exclusive block offsets
}

// add block offsets; also init g_pos and compute dinv (fused)
__global__ void k_scan_add()
{
    int i = blockIdx.x * blockDim.x + threadIdx.x;
    if (i < NN) {
        int o = g_excl[i] + g_btop[i >> 10];
        g_off[i] = o;
        g_pos[i] = o;
        g_dinv[i] = rsqrtf(g_deg[i]);                // deg >= 1 always
    }
    if (i == 0) g_off[NN] = 2 * EE;                  // total is deterministic
}

// fill CSR: each undirected edge contributes both directions with coef c
__global__ void k_fill(const float* __restrict__ ew,
                       const int* __restrict__ ui,
                       const int* __restrict__ ii)
{
    int e = blockIdx.x * blockDim.x + threadIdx.x;
    if (e >= EE) return;
    float w = fmaxf(ew[e], 1e-6f);
    int u = ui[e];
    int v = ii[e] + UU;
    float c = g_dinv[u] * w * g_dinv[v];
    int cb = __float_as_int(c);
    int p0 = atomicAdd(&g_pos[v], 1);
    g_edge[p0] = make_int2(u, cb);
    int p1 = atomicAdd(&g_pos[u], 1);
    g_edge[p1] = make_int2(v, cb);
}

// ---------------------------------------------------------------------------
// user L0 embedding: l2norm(user_w) -> x[0:U], acc[0:U].  One warp per user.
__global__ void k_user(const float* __restrict__ uw)
{
    int warp = (blockIdx.x * blockDim.x + threadIdx.x) >> 5;
    int lane = threadIdx.x & 31;
    if (warp >= UU) return;
    float2 v = ((const float2*)(uw + (size_t)warp * DD))[lane];
    float ss = v.x * v.x + v.y * v.y;
    #pragma unroll
    for (int o = 16; o; o >>= 1) ss += __shfl_xor_sync(0xffffffffu, ss, o);
    float inv = 1.0f / fmaxf(sqrtf(ss), 1e-12f);
    float2 r = make_float2(v.x * inv, v.y * inv);
    ((float2*)(g_x   + (size_t)warp * DD))[lane] = r;
    ((float2*)(g_acc + (size_t)warp * DD))[lane] = r;
}

// item L0: l2norm( [audio | artist+album] @ W^T + b ). One warp per item,
// 8 items per 256-thread block, W^T staged k-major in shared (conflict-free).
__global__ void k_item(const float* __restrict__ audio,
                       const float* __restrict__ artw,
                       const float* __restrict__ albw,
                       const float* __restrict__ W,     // [64,128] row-major
                       const float* __restrict__ b,
                       const int* __restrict__ aid,
                       const int* __restrict__ bid)
{
    __shared__ float Wsh[128 * 64];     // Wsh[k*64+d] = W[d*128+k]
    __shared__ float fsh[8][128];
    for (int idx = threadIdx.x; idx < 128 * 64; idx += blockDim.x) {
        int d = idx & 63, k = idx >> 6;
        Wsh[idx] = W[d * 128 + k];
    }
    __syncthreads();

    int warp = threadIdx.x >> 5;
    int lane = threadIdx.x & 31;
    int item = blockIdx.x * 8 + warp;
    if (item >= II) return;

    int a = aid[item];
    int bb = bid[item];
    float2 au = ((const float2*)(audio + (size_t)item * DD))[lane];
    float2 m0 = ((const float2*)(artw  + (size_t)a    * DD))[lane];
    float2 m1 = ((const float2*)(albw  + (size_t)bb   * DD))[lane];
    ((float2*)(fsh[warp]))[lane]      = au;
    ((float2*)(fsh[warp] + 64))[lane] = make_float2(m0.x + m1.x, m0.y + m1.y);
    __syncwarp();

    float a0 = 0.f, a1 = 0.f;
    #pragma unroll
    for (int k = 0; k < 128; k++) {
        float f = fsh[warp][k];
        a0 = fmaf(f, Wsh[k * 64 + lane],      a0);
        a1 = fmaf(f, Wsh[k * 64 + lane + 32], a1);
    }
    a0 += b[lane];
    a1 += b[lane + 32];
    float ss = a0 * a0 + a1 * a1;
    #pragma unroll
    for (int o = 16; o; o >>= 1) ss += __shfl_xor_sync(0xffffffffu, ss, o);
    float inv = 1.0f / fmaxf(sqrtf(ss), 1e-12f);
    size_t row = (size_t)(UU + item) * DD;
    g_x  [row + lane]      = a0 * inv;
    g_x  [row + lane + 32] = a1 * inv;
    g_acc[row + lane]      = a0 * inv;
    g_acc[row + lane + 32] = a1 * inv;
}

// ---------------------------------------------------------------------------
// one LGConv layer: warp per dest node; pure gather + register reduce.
// parity selects ping-pong; accAdd folds the running-sum of the PREVIOUS layer.
__global__ void k_prop(int parity, int accAdd)
{
    const float* __restrict__ x  = parity ? g_xn : g_x;
    float*       __restrict__ xn = parity ? g_x  : g_xn;

    int warp = (blockIdx.x * blockDim.x + threadIdx.x) >> 5;
    int lane = threadIdx.x & 31;
    if (warp >= NN) return;
    int dest = warp;

    float2 v = ((const float2*)(x + (size_t)dest * DD))[lane];
    float di = g_dinv[dest];
    float cs = di * di;                       // self-loop coefficient
    float rx = cs * v.x, ry = cs * v.y;

    if (accAdd) {
        float2* ar = (float2*)(g_acc + (size_t)dest * DD);
        float2 a = ar[lane];
        a.x += v.x; a.y += v.y;
        ar[lane] = a;
    }

    int e   = g_off[dest];
    int end = g_off[dest + 1];
    for (; e + 4 <= end; e += 4) {
        int2 e0 = __ldg(&g_edge[e]);
        int2 e1 = __ldg(&g_edge[e + 1]);
        int2 e2 = __ldg(&g_edge[e + 2]);
        int2 e3 = __ldg(&g_edge[e + 3]);
        float2 v0 = __ldg(&((const float2*)(x + (size_t)e0.x * DD))[lane]);
        float2 v1 = __ldg(&((const float2*)(x + (size_t)e1.x * DD))[lane]);
        float2 v2 = __ldg(&((const float2*)(x + (size_t)e2.x * DD))[lane]);
        float2 v3 = __ldg(&((const float2*)(x + (size_t)e3.x * DD))[lane]);
        rx = fmaf(__int_as_float(e0.y), v0.x, rx); ry = fmaf(__int_as_float(e0.y), v0.y, ry);
        rx = fmaf(__int_as_float(e1.y), v1.x, rx); ry = fmaf(__int_as_float(e1.y), v1.y, ry);
        rx = fmaf(__int_as_float(e2.y), v2.x, rx); ry = fmaf(__int_as_float(e2.y), v2.y, ry);
        rx = fmaf(__int_as_float(e3.y), v3.x, rx); ry = fmaf(__int_as_float(e3.y), v3.y, ry);
    }
    for (; e < end; e++) {
        int2 ee = __ldg(&g_edge[e]);
        float2 vv = __ldg(&((const float2*)(x + (size_t)ee.x * DD))[lane]);
        rx = fmaf(__int_as_float(ee.y), vv.x, rx);
        ry = fmaf(__int_as_float(ee.y), vv.y, ry);
    }
    ((float2*)(xn + (size_t)dest * DD))[lane] = make_float2(rx, ry);
}

// out = l2norm( (acc + x3) / 4 ).  x3 lives in g_xn after layer 2.
__global__ void k_final(float* __restrict__ out)
{
    int warp = (blockIdx.x * blockDim.x + threadIdx.x) >> 5;
    int lane = threadIdx.x & 31;
    if (warp >= NN) return;
    float2 a  = ((const float2*)(g_acc + (size_t)warp * DD))[lane];
    float2 xl = ((const float2*)(g_xn  + (size_t)warp * DD))[lane];
    float sx = (a.x + xl.x) * 0.25f;
    float sy = (a.y + xl.y) * 0.25f;
    float ss = sx * sx + sy * sy;
    #pragma unroll
    for (int o = 16; o; o >>= 1) ss += __shfl_xor_sync(0xffffffffu, ss, o);
    float inv = 1.0f / fmaxf(sqrtf(ss), 1e-12f);
    ((float2*)(out + (size_t)warp * DD))[lane] = make_float2(sx * inv, sy * inv);
}

// ---------------------------------------------------------------------------
extern "C" void kernel_launch(void* const* d_in, const int* in_sizes, int n_in,
                              void* d_out, int out_size)
{
    const float* user_w     = (const float*)d_in[0];
    const float* item_audio = (const float*)d_in[1];
    const float* artist_w   = (const float*)d_in[2];
    const float* album_w    = (const float*)d_in[3];
    const float* proj_W     = (const float*)d_in[4];
    const float* proj_b     = (const float*)d_in[5];
    const float* edge_w     = (const float*)d_in[6];
    const int*   u_idx      = (const int*)  d_in[7];
    const int*   i_idx      = (const int*)  d_in[8];
    const int*   artist_ids = (const int*)  d_in[9];
    const int*   album_ids  = (const int*)  d_in[10];
    float* out = (float*)d_out;

    const int T = 256;
    int nBlocksN = (NN + T - 1) / T;
    int nBlocksE = (EE + T - 1) / T;
    int nWarpBlocksN = (NN * 32 + T - 1) / T;   // warp-per-node kernels
    int nWarpBlocksU = (UU * 32 + T - 1) / T;
    int nBlocksItem  = (II + 7) / 8;

    // graph build
    k_init<<<nBlocksN, T>>>();
    k_edge_stats<<<nBlocksE, T>>>(edge_w, u_idx, i_idx);
    k_scan_block<<<NB, 1024>>>();
    k_scan_tops<<<1, 256>>>();
    k_scan_add<<<nBlocksN, T>>>();
    k_fill<<<nBlocksE, T>>>(edge_w, u_idx, i_idx);

    // L0 embeddings (also initialize acc = x0)
    k_user<<<nWarpBlocksU, T>>>(user_w);
    k_item<<<nBlocksItem, T>>>(item_audio, artist_w, album_w, proj_W, proj_b,
                               artist_ids, album_ids);

    // 3 LGConv layers with fused running sum
    k_prop<<<nWarpBlocksN, T>>>(0, 0);   // x0 -> x1 (in g_xn)
    k_prop<<<nWarpBlocksN, T>>>(1, 1);   // acc += x1; x1 -> x2 (in g_x)
    k_prop<<<nWarpBlocksN, T>>>(0, 1);   // acc += x2; x2 -> x3 (in g_xn)

    // out = l2norm((acc + x3)/4)
    k_final<<<nWarpBlocksN, T>>>(out);
}